// round 7
// baseline (speedup 1.0000x reference)
#include <cuda_runtime.h>
#include <cuda_fp16.h>
#include <cstdint>

// ---------------------------------------------------------------------------
// net: conv3x3(3->10)+relu -> conv3x3(10->20)+relu -> FC(2880->500) ->
//      heaviside(>=0 -> 1 else 0) -> FC(500->10)
// B = 65536
//
// conv: packed fp32 (fma.rn.f32x2, FFMA2) -> 2x FMA rate vs scalar FFMA.
// FC1: tensor cores (mma.sync fp16), |v| < 6e-4 recomputed in fp64 from
//      fp16 hi+lo activation pair (exact to ~1e-7).
// ---------------------------------------------------------------------------

#define B_TOTAL 65536
#define KDIM 2880
#define NOUT 500
#define NPAD 512
#define FIX_CAP (1u*1024u*1024u)
#define T_FIX 6e-4f

__device__ __half        g_a0[(size_t)B_TOTAL * KDIM];   // fp16 activations (hi)
__device__ __half        g_a1[(size_t)B_TOTAL * KDIM];   // fp16 residual (lo)
__device__ __half        g_b0[(size_t)NPAD * KDIM];      // fp16 weights
__device__ unsigned char g_s[(size_t)B_TOTAL * NOUT];    // heaviside bytes
__device__ unsigned int  g_fix[FIX_CAP];                 // fixup worklist
__device__ unsigned int  g_nfix;

// ---- packed fp32 helpers ----
typedef unsigned long long ull;

__device__ __forceinline__ ull pack2(float lo, float hi) {
    ull d;
    asm("mov.b64 %0, {%1,%2};" : "=l"(d)
        : "r"(__float_as_uint(lo)), "r"(__float_as_uint(hi)));
    return d;
}
__device__ __forceinline__ void unpack2(ull v, float& lo, float& hi) {
    unsigned int a, b;
    asm("mov.b64 {%0,%1}, %2;" : "=r"(a), "=r"(b) : "l"(v));
    lo = __uint_as_float(a); hi = __uint_as_float(b);
}
__device__ __forceinline__ void fma2(ull& d, ull a, ull b) {
    asm("fma.rn.f32x2 %0, %1, %2, %3;" : "=l"(d) : "l"(a), "l"(b), "l"(d));
}

__device__ __forceinline__ uint32_t smem_u32(const void* p) {
    uint32_t a;
    asm("{ .reg .u64 t; cvta.to.shared.u64 t, %1; cvt.u32.u64 %0, t; }" : "=r"(a) : "l"(p));
    return a;
}
__device__ __forceinline__ void cp16(uint32_t dst, const void* src) {
    asm volatile("cp.async.cg.shared.global [%0], [%1], 16;" :: "r"(dst), "l"(src));
}
__device__ __forceinline__ void ldx4(uint32_t* r, uint32_t addr) {
    asm volatile("ldmatrix.sync.aligned.m8n8.x4.shared.b16 {%0,%1,%2,%3}, [%4];"
                 : "=r"(r[0]), "=r"(r[1]), "=r"(r[2]), "=r"(r[3]) : "r"(addr));
}
__device__ __forceinline__ void mma16816(float* c, const uint32_t* a,
                                         uint32_t b0, uint32_t b1) {
    asm volatile(
        "mma.sync.aligned.m16n8k16.row.col.f32.f16.f16.f32 "
        "{%0,%1,%2,%3}, {%4,%5,%6,%7}, {%8,%9}, {%0,%1,%2,%3};"
        : "+f"(c[0]), "+f"(c[1]), "+f"(c[2]), "+f"(c[3])
        : "r"(a[0]), "r"(a[1]), "r"(a[2]), "r"(a[3]), "r"(b0), "r"(b1));
}

// ---------------------------------------------------------------------------
// Kernel 0: weight fp16 conversion + counter reset
// ---------------------------------------------------------------------------
__global__ __launch_bounds__(256)
void prep_kernel(const float* __restrict__ W)
{
    const size_t idx = (size_t)blockIdx.x * 256 + threadIdx.x;
    if (idx == 0) g_nfix = 0;
    if (idx >= (size_t)NPAD * KDIM) return;
    const int n = (int)(idx / KDIM);
    const float w = (n < NOUT) ? W[(size_t)n * KDIM + (idx % KDIM)] : 0.f;
    g_b0[idx] = __float2half_rn(w);
}

// ---------------------------------------------------------------------------
// Kernel 1: fused conv1+relu+conv2+relu, 4 samples/CTA, packed f32x2 math.
// ---------------------------------------------------------------------------
#define CONV_SMEM (12982 * 4)

__global__ __launch_bounds__(256, 2)
void conv_fused_kernel(const float* __restrict__ x,
                       const float* __restrict__ w1, const float* __restrict__ b1,
                       const float* __restrict__ w2, const float* __restrict__ b2)
{
    extern __shared__ float sm[];
    float* sw1 = sm;            // 270
    float* sw2 = sm + 270;      // 1800
    float* sx  = sm + 2070;     // 4*768
    float* sh1 = sm + 5142;     // 4*1960

    const int tid = threadIdx.x;
    const size_t b0 = (size_t)blockIdx.x * 4;

    const float* xb = x + b0 * 768;
    #pragma unroll
    for (int i = 0; i < 12; ++i) sx[i * 256 + tid] = xb[i * 256 + tid];
    for (int i = tid; i < 270; i += 256)  sw1[i] = w1[i];
    for (int i = tid; i < 1800; i += 256) sw2[i] = w2[i];
    __syncthreads();

    // ---- conv1: 280 tasks, 2 oc x 14 ox each, packed over ox pairs ----
    for (int t = tid; t < 280; t += 256) {
        const int s   = t / 70;
        const int r   = t % 70;
        const int ocg = r / 14;
        const int oy  = r % 14;
        const int oc  = ocg * 2;

        ull acc[2][7];
        {
            const float bz0 = b1[oc], bz1 = b1[oc + 1];
            #pragma unroll
            for (int j2 = 0; j2 < 7; j2++) {
                acc[0][j2] = pack2(bz0, bz0);
                acc[1][j2] = pack2(bz1, bz1);
            }
        }

        #pragma unroll
        for (int ic = 0; ic < 3; ic++) {
            #pragma unroll
            for (int ky = 0; ky < 3; ky++) {
                const float* row = sx + s * 768 + ic * 256 + (oy + ky) * 16;
                ull P[15];
                {
                    float xv[16];
                    #pragma unroll
                    for (int i = 0; i < 16; i++) xv[i] = row[i];
                    #pragma unroll
                    for (int i = 0; i < 15; i++) P[i] = pack2(xv[i], xv[i + 1]);
                }
                ull wk[2][3];
                #pragma unroll
                for (int j = 0; j < 2; j++)
                    #pragma unroll
                    for (int kx = 0; kx < 3; kx++) {
                        const float w = sw1[(oc + j) * 27 + ic * 9 + ky * 3 + kx];
                        wk[j][kx] = pack2(w, w);
                    }
                #pragma unroll
                for (int j2 = 0; j2 < 7; j2++)
                    #pragma unroll
                    for (int j = 0; j < 2; j++) {
                        fma2(acc[j][j2], wk[j][0], P[2 * j2]);
                        fma2(acc[j][j2], wk[j][1], P[2 * j2 + 1]);
                        fma2(acc[j][j2], wk[j][2], P[2 * j2 + 2]);
                    }
            }
        }
        #pragma unroll
        for (int j = 0; j < 2; j++) {
            float* o = sh1 + s * 1960 + (oc + j) * 196 + oy * 14;
            #pragma unroll
            for (int j2 = 0; j2 < 7; j2++) {
                float v0, v1;
                unpack2(acc[j][j2], v0, v1);
                o[2 * j2]     = fmaxf(v0, 0.f);
                o[2 * j2 + 1] = fmaxf(v1, 0.f);
            }
        }
    }
    __syncthreads();

    // ---- conv2: 240 tasks, 4 oc x 12 ox each, packed over ox pairs ----
    if (tid < 240) {
        const int s   = tid / 60;
        const int r   = tid % 60;
        const int ocg = r / 12;
        const int oy  = r % 12;
        const int oc  = ocg * 4;

        ull acc[4][6];
        #pragma unroll
        for (int j = 0; j < 4; j++) {
            const float bz = b2[oc + j];
            #pragma unroll
            for (int j2 = 0; j2 < 6; j2++) acc[j][j2] = pack2(bz, bz);
        }

        for (int ic = 0; ic < 10; ic++) {
            #pragma unroll
            for (int ky = 0; ky < 3; ky++) {
                const float* row = sh1 + s * 1960 + ic * 196 + (oy + ky) * 14;
                ull P[13];
                {
                    float xv[14];
                    #pragma unroll
                    for (int i = 0; i < 14; i++) xv[i] = row[i];
                    #pragma unroll
                    for (int i = 0; i < 13; i++) P[i] = pack2(xv[i], xv[i + 1]);
                }
                ull wk[4][3];
                #pragma unroll
                for (int j = 0; j < 4; j++)
                    #pragma unroll
                    for (int kx = 0; kx < 3; kx++) {
                        const float w = sw2[(oc + j) * 90 + ic * 9 + ky * 3 + kx];
                        wk[j][kx] = pack2(w, w);
                    }
                #pragma unroll
                for (int j2 = 0; j2 < 6; j2++)
                    #pragma unroll
                    for (int j = 0; j < 4; j++) {
                        fma2(acc[j][j2], wk[j][0], P[2 * j2]);
                        fma2(acc[j][j2], wk[j][1], P[2 * j2 + 1]);
                        fma2(acc[j][j2], wk[j][2], P[2 * j2 + 2]);
                    }
            }
        }

        const size_t sbase = (b0 + s) * KDIM + oc * 144 + oy * 12;
        #pragma unroll
        for (int j = 0; j < 4; j++) {
            float v[12];
            #pragma unroll
            for (int j2 = 0; j2 < 6; j2++) {
                float a, b;
                unpack2(acc[j][j2], a, b);
                v[2 * j2]     = fmaxf(a, 0.f);
                v[2 * j2 + 1] = fmaxf(b, 0.f);
            }
            __half2 h0[6], h1[6];
            #pragma unroll
            for (int q = 0; q < 6; q++) {
                const __half hia = __float2half_rn(v[2*q]);
                const __half hib = __float2half_rn(v[2*q+1]);
                const __half loa = __float2half_rn(v[2*q]   - __half2float(hia));
                const __half lob = __float2half_rn(v[2*q+1] - __half2float(hib));
                h0[q] = __halves2half2(hia, hib);
                h1[q] = __halves2half2(loa, lob);
            }
            // 12 halfs = 24B: base offset is 8B-aligned (oy*24), so use 3x uint2
            char* p0 = reinterpret_cast<char*>(g_a0 + sbase + j * 144);
            char* p1 = reinterpret_cast<char*>(g_a1 + sbase + j * 144);
            const uint2* s0 = reinterpret_cast<const uint2*>(h0);
            const uint2* s1 = reinterpret_cast<const uint2*>(h1);
            #pragma unroll
            for (int q = 0; q < 3; q++) {
                reinterpret_cast<uint2*>(p0)[q] = s0[q];
                reinterpret_cast<uint2*>(p1)[q] = s1[q];
            }
        }
    }
}

// ---------------------------------------------------------------------------
// Kernel 2: FC1 via mma.sync fp16, 128x128 tile, BK=32, 4-stage cp.async.
// Epilogue: signs staged in smem -> coalesced 4B global stores.
// ---------------------------------------------------------------------------
#define BK 32
#define PITCH 80
#define TILE_BYTES (128 * PITCH)      // 10240
#define STAGE_BYTES (2 * TILE_BYTES)  // 20480 : A, B
#define NSTAGE 4
#define FC1_SMEM (NSTAGE * STAGE_BYTES)
#define NITER (KDIM / BK)             // 90
#define SPITCH 144                    // sign staging pitch (bytes)

__device__ __forceinline__ void load_stage(uint32_t sb,
                                           const __half* ga,
                                           const __half* gb,
                                           int k0, int tid)
{
    const __half* srcs[2] = { ga + k0, gb + k0 };
    #pragma unroll
    for (int t = 0; t < 2; ++t) {
        #pragma unroll
        for (int h = 0; h < 2; ++h) {
            const int idx = h * 256 + tid;        // 0..511
            const int r = idx >> 2, c = idx & 3;
            cp16(sb + t * TILE_BYTES + r * PITCH + c * 16,
                 srcs[t] + (size_t)r * KDIM + c * 8);
        }
    }
}

__global__ __launch_bounds__(256, 2)
void fc1_mma_kernel(const float* __restrict__ bias, int m_base)
{
    extern __shared__ char smc[];
    const uint32_t smb = smem_u32(smc);
    const int tid  = threadIdx.x;
    const int lane = tid & 31;
    const int wid  = tid >> 5;
    const int n0 = blockIdx.x * 128;
    const int m0 = m_base + blockIdx.y * 128;

    const int m_off = (wid & 1) * 64;
    const int n_off = (wid >> 1) * 32;

    const __half* ga = g_a0 + (size_t)m0 * KDIM;
    const __half* gb = g_b0 + (size_t)n0 * KDIM;

    float acc[4][4][4];
    #pragma unroll
    for (int i = 0; i < 4; i++)
        #pragma unroll
        for (int j = 0; j < 4; j++)
            #pragma unroll
            for (int q = 0; q < 4; q++) acc[i][j][q] = 0.f;

    #pragma unroll
    for (int p = 0; p < 3; ++p) {
        load_stage(smb + p * STAGE_BYTES, ga, gb, p * BK, tid);
        asm volatile("cp.async.commit_group;");
    }

    const uint32_t a_lane = (uint32_t)(lane & 15) * PITCH + (uint32_t)(lane >> 4) * 16;
    const uint32_t b_lane = (uint32_t)(lane & 7) * PITCH + (uint32_t)(lane >> 3) * 16;

    for (int i = 0; i < NITER; ++i) {
        asm volatile("cp.async.wait_group 2;");
        __syncthreads();
        if (i + 3 < NITER)
            load_stage(smb + ((i + 3) & 3) * STAGE_BYTES,
                       ga, gb, (i + 3) * BK, tid);
        asm volatile("cp.async.commit_group;");

        const uint32_t sb = smb + (i & 3) * STAGE_BYTES;
        const uint32_t Ab = sb;
        const uint32_t Bb = sb + TILE_BYTES;

        uint32_t bf[4][4];
        #pragma unroll
        for (int nt = 0; nt < 4; ++nt)
            ldx4(bf[nt], Bb + (uint32_t)(n_off + nt * 8) * PITCH + b_lane);

        #pragma unroll
        for (int kk = 0; kk < 2; ++kk) {
            uint32_t af[4][4];
            #pragma unroll
            for (int mt = 0; mt < 4; ++mt)
                ldx4(af[mt], Ab + (uint32_t)(m_off + mt * 16) * PITCH + a_lane
                             + (uint32_t)kk * 32);
            #pragma unroll
            for (int mt = 0; mt < 4; ++mt)
                #pragma unroll
                for (int nt = 0; nt < 4; ++nt)
                    mma16816(acc[mt][nt], af[mt], bf[nt][kk*2], bf[nt][kk*2+1]);
        }
    }

    // ---- epilogue: bias + heaviside -> smem staging, flag near-zeros ----
    __syncthreads();   // all warps done reading stage buffers
    unsigned char* sbyte = reinterpret_cast<unsigned char*>(smc);

    const int g  = lane >> 2;
    const int t2 = (lane & 3) * 2;
    #pragma unroll
    for (int mt = 0; mt < 4; ++mt) {
        const int mlA = m_off + mt * 16 + g;
        const int mlB = mlA + 8;
        #pragma unroll
        for (int nt = 0; nt < 4; ++nt) {
            const int nl = n_off + nt * 8 + t2;
            const int n  = n0 + nl;
            if (n >= NOUT) continue;
            const float bn0 = __ldg(&bias[n]);
            const float bn1 = __ldg(&bias[n + 1]);

            const float vA0 = acc[mt][nt][0] + bn0;
            const float vA1 = acc[mt][nt][1] + bn1;
            const float vB0 = acc[mt][nt][2] + bn0;
            const float vB1 = acc[mt][nt][3] + bn1;

            sbyte[mlA * SPITCH + nl]     = vA0 >= 0.f;
            sbyte[mlA * SPITCH + nl + 1] = vA1 >= 0.f;
            sbyte[mlB * SPITCH + nl]     = vB0 >= 0.f;
            sbyte[mlB * SPITCH + nl + 1] = vB1 >= 0.f;

            const int mA = m0 + mlA, mB = m0 + mlB;
            if (fabsf(vA0) < T_FIX) {
                unsigned int ix = atomicAdd(&g_nfix, 1u);
                if (ix < FIX_CAP) g_fix[ix] = ((unsigned int)mA << 9) | (unsigned int)n;
            }
            if (fabsf(vA1) < T_FIX) {
                unsigned int ix = atomicAdd(&g_nfix, 1u);
                if (ix < FIX_CAP) g_fix[ix] = ((unsigned int)mA << 9) | (unsigned int)(n+1);
            }
            if (fabsf(vB0) < T_FIX) {
                unsigned int ix = atomicAdd(&g_nfix, 1u);
                if (ix < FIX_CAP) g_fix[ix] = ((unsigned int)mB << 9) | (unsigned int)n;
            }
            if (fabsf(vB1) < T_FIX) {
                unsigned int ix = atomicAdd(&g_nfix, 1u);
                if (ix < FIX_CAP) g_fix[ix] = ((unsigned int)mB << 9) | (unsigned int)(n+1);
            }
        }
    }
    __syncthreads();

    // coalesced store: 128 rows x (up to 32) words
    const int ncols  = (n0 + 128 <= NOUT) ? 128 : (NOUT - n0);   // 128 or 116
    const int nwords = ncols >> 2;                                // 32 or 29
    #pragma unroll
    for (int it = 0; it < 16; ++it) {
        const int idx = it * 256 + tid;
        const int r = idx >> 5, w = idx & 31;
        if (w < nwords) {
            const uint32_t val = *reinterpret_cast<uint32_t*>(sbyte + r * SPITCH + w * 4);
            *reinterpret_cast<uint32_t*>(g_s + (size_t)(m0 + r) * NOUT + n0 + w * 4) = val;
        }
    }
}

// ---------------------------------------------------------------------------
// Kernel 3: fp64 recompute of flagged near-zero dots (warp per entry)
// ---------------------------------------------------------------------------
__global__ __launch_bounds__(256)
void fixup_kernel(const float* __restrict__ W, const float* __restrict__ bias)
{
    const int lane = threadIdx.x & 31;
    const int warp = threadIdx.x >> 5;
    unsigned int total = g_nfix;
    if (total > FIX_CAP) total = FIX_CAP;

    for (unsigned int e = blockIdx.x * 8 + warp; e < total; e += gridDim.x * 8) {
        const unsigned int ent = g_fix[e];
        const int m = (int)(ent >> 9);
        const int n = (int)(ent & 511u);
        const __half* h0 = g_a0 + (size_t)m * KDIM;
        const __half* h1 = g_a1 + (size_t)m * KDIM;
        const float* wr = W + (size_t)n * KDIM;
        double acc = 0.0;
        #pragma unroll 5
        for (int k = lane; k < KDIM; k += 32) {
            const double h = (double)__half2float(h0[k]) + (double)__half2float(h1[k]);
            acc += h * (double)wr[k];
        }
        #pragma unroll
        for (int off = 16; off > 0; off >>= 1)
            acc += __shfl_down_sync(0xffffffffu, acc, off);
        if (lane == 0) {
            const double v = acc + (double)bias[n];
            g_s[(size_t)m * NOUT + n] = (v >= 0.0) ? 1 : 0;
        }
    }
}

// ---------------------------------------------------------------------------
// Kernel 4: FC2 on binary signs, smem-staged, quad per sample
// ---------------------------------------------------------------------------
__global__ __launch_bounds__(256)
void fc2_kernel(const float* __restrict__ W2, const float* __restrict__ b2,
                float* __restrict__ out)
{
    __shared__ float sw[5000];                 // [10][500]
    __shared__ unsigned char ss[64 * 500];     // 64 sample rows

    const int tid = threadIdx.x;
    for (int i = tid; i < 5000; i += 256) sw[i] = W2[i];

    const size_t base = (size_t)blockIdx.x * 64;
    const uint4* gsrc = reinterpret_cast<const uint4*>(g_s + base * NOUT);
    uint4* sdst = reinterpret_cast<uint4*>(ss);
    #pragma unroll
    for (int i = 0; i < 8; ++i) {
        const int idx = i * 256 + tid;
        if (idx < 2000) sdst[idx] = gsrc[idx];
    }
    __syncthreads();

    const int s = tid >> 2;
    const int q = tid & 3;
    const unsigned char* srow = ss + s * NOUT + q * 125;
    const int nq = q * 125;

    float acc[10];
    #pragma unroll
    for (int i = 0; i < 10; i++) acc[i] = 0.f;

    for (int j = 0; j < 125; ++j) {
        const float sv = (float)srow[j];
        #pragma unroll
        for (int i = 0; i < 10; i++)
            acc[i] += sv * sw[i * NOUT + nq + j];
    }

    #pragma unroll
    for (int i = 0; i < 10; i++) {
        acc[i] += __shfl_xor_sync(0xffffffffu, acc[i], 1);
        acc[i] += __shfl_xor_sync(0xffffffffu, acc[i], 2);
    }

    if (q == 0) {
        float* o = out + (base + s) * 10;
        #pragma unroll
        for (int i = 0; i < 10; i++) o[i] = acc[i] + b2[i];
    }
}

// ---------------------------------------------------------------------------
extern "C" void kernel_launch(void* const* d_in, const int* in_sizes, int n_in,
                              void* d_out, int out_size)
{
    const float* x    = (const float*)d_in[0];
    const float* w1   = (const float*)d_in[1];
    const float* b1   = (const float*)d_in[2];
    const float* w2   = (const float*)d_in[3];
    const float* b2   = (const float*)d_in[4];
    const float* fcw  = (const float*)d_in[5];
    const float* fcb  = (const float*)d_in[6];
    const float* fc2w = (const float*)d_in[7];
    const float* fc2b = (const float*)d_in[8];

    cudaFuncSetAttribute(conv_fused_kernel,
                         cudaFuncAttributeMaxDynamicSharedMemorySize, CONV_SMEM);
    cudaFuncSetAttribute(fc1_mma_kernel,
                         cudaFuncAttributeMaxDynamicSharedMemorySize, FC1_SMEM);

    prep_kernel<<<(NPAD * KDIM + 255) / 256, 256>>>(fcw);
    conv_fused_kernel<<<B_TOTAL / 4, 256, CONV_SMEM>>>(x, w1, b1, w2, b2);

    dim3 g1(4, 256);
    fc1_mma_kernel<<<g1, 256, FC1_SMEM>>>(fcb, 0);
    fc1_mma_kernel<<<g1, 256, FC1_SMEM>>>(fcb, 32768);

    fixup_kernel<<<1024, 256>>>(fcw, fcb);
    fc2_kernel<<<B_TOTAL / 64, 256>>>(fc2w, fc2b, (float*)d_out);
}